// round 8
// baseline (speedup 1.0000x reference)
#include <cuda_runtime.h>
#include <math.h>

#define SLEN 4096
#define DIM  256
#define HID  512
#define H4   2048
#define NE   2000
#define NL   20
#define GCTA 64      // CTAs per direction
#define HPC  8       // h-indices per CTA (HID / GCTA)
#define LTHR 256     // threads per LSTM CTA (8 warps)

// ---------------- device scratch (static: no runtime allocation) -------------
__device__ float g_xw[2][SLEN][H4];        // 64 MB: x@Wi^T + b
__device__ float g_hs[2][SLEN][HID];       // 16 MB: h history for epilogue
__device__ float g_hring[2][2][HID];       // 4 KB hot ring: [dir][slot][h]
__device__ unsigned g_flag[2][2][GCTA];    // 1 KB flags: [dir][slot][cta]
__device__ float g_scores[SLEN];

__device__ __forceinline__ float tanh_fast(float x) {
    float r;
    asm("tanh.approx.f32 %0, %1;" : "=f"(r) : "f"(x));
    return r;
}
__device__ __forceinline__ float sigmoid_fast(float x) {
    return fmaf(tanh_fast(0.5f * x), 0.5f, 0.5f);
}

// 16-byte .cg load returning two packed u64 (f32x2 pairs) -- read-only data
__device__ __forceinline__ void ldcg_v2u64(const void* p,
                                           unsigned long long& a,
                                           unsigned long long& b) {
    asm volatile("ld.global.cg.v2.u64 {%0,%1}, [%2];"
                 : "=l"(a), "=l"(b) : "l"(p) : "memory");
}

__device__ __forceinline__ unsigned long long ld_relaxed_u64(const void* p) {
    unsigned long long v;
    asm volatile("ld.relaxed.gpu.global.u64 %0, [%1];" : "=l"(v) : "l"(p) : "memory");
    return v;
}
__device__ __forceinline__ void st_relaxed_u32(unsigned* p, unsigned v) {
    asm volatile("st.relaxed.gpu.global.u32 [%0], %1;" :: "l"(p), "r"(v) : "memory");
}
__device__ __forceinline__ void fence_acqrel_gpu() {
    asm volatile("fence.acq_rel.gpu;" ::: "memory");
}

// padded smem index: +2 words every 16 -> stride 18/warp-slice, conflict-free LDS.64
__device__ __forceinline__ int pidx(int i) { return i + ((i >> 4) << 1); }

// ---------------- kernel 1: xW GEMM + flag reset ------------------------------
// C[m][n] = sum_k emb[sent[m]][k] * Wi[n][k] + b[n];  M=4096, N=2048, K=256
__global__ void __launch_bounds__(256) xw_gemm_kernel(
    const int* __restrict__ sent, const float* __restrict__ emb,
    const float* __restrict__ Wi_f, const float* __restrict__ b_f,
    const float* __restrict__ Wi_b, const float* __restrict__ b_b)
{
    // reset flags each run (stream-ordered before lstm_kernel)
    if (blockIdx.x == 0 && blockIdx.y == 0 && blockIdx.z == 0 && threadIdx.x < 4 * GCTA)
        (&g_flag[0][0][0])[threadIdx.x] = 0u;

    const int dir = blockIdx.z;
    const float* __restrict__ Wi   = dir ? Wi_b : Wi_f;
    const float* __restrict__ bias = dir ? b_b : b_f;
    const int n0 = blockIdx.x * 64;
    const int m0 = blockIdx.y * 64;

    __shared__ float As[16][64];
    __shared__ float Bs[16][64];
    __shared__ int   rows[64];

    const int tid = threadIdx.x;
    if (tid < 64) rows[tid] = sent[m0 + tid];
    __syncthreads();

    const int lm = tid >> 2;
    const int lk = (tid & 3) * 4;
    const int ty = (tid >> 4) * 4;
    const int tx = (tid & 15) * 4;

    float acc[4][4];
    #pragma unroll
    for (int i = 0; i < 4; i++)
        #pragma unroll
        for (int j = 0; j < 4; j++) acc[i][j] = 0.0f;

    for (int k0 = 0; k0 < DIM; k0 += 16) {
        float4 a = *(const float4*)&emb[(long)rows[lm] * DIM + k0 + lk];
        float4 b = *(const float4*)&Wi[(long)(n0 + lm) * DIM + k0 + lk];
        __syncthreads();
        As[lk + 0][lm] = a.x; As[lk + 1][lm] = a.y;
        As[lk + 2][lm] = a.z; As[lk + 3][lm] = a.w;
        Bs[lk + 0][lm] = b.x; Bs[lk + 1][lm] = b.y;
        Bs[lk + 2][lm] = b.z; Bs[lk + 3][lm] = b.w;
        __syncthreads();
        #pragma unroll
        for (int kk = 0; kk < 16; kk++) {
            float4 a4 = *(const float4*)&As[kk][ty];
            float4 b4 = *(const float4*)&Bs[kk][tx];
            float av[4] = {a4.x, a4.y, a4.z, a4.w};
            float bv[4] = {b4.x, b4.y, b4.z, b4.w};
            #pragma unroll
            for (int i = 0; i < 4; i++)
                #pragma unroll
                for (int j = 0; j < 4; j++)
                    acc[i][j] = fmaf(av[i], bv[j], acc[i][j]);
        }
    }

    float4 bb = *(const float4*)&bias[n0 + tx];
    float bvv[4] = {bb.x, bb.y, bb.z, bb.w};
    #pragma unroll
    for (int i = 0; i < 4; i++) {
        float4 o;
        o.x = acc[i][0] + bvv[0];
        o.y = acc[i][1] + bvv[1];
        o.z = acc[i][2] + bvv[2];
        o.w = acc[i][3] + bvv[3];
        *(float4*)&g_xw[dir][m0 + ty + i][n0 + tx] = o;
    }
}

// ---------------- kernel 2: persistent BiLSTM, flag+ring sync -----------------
__global__ void __launch_bounds__(LTHR) lstm_kernel(
    const float* __restrict__ Wh_f, const float* __restrict__ Wh_b)
{
    __shared__ __align__(16) float sm_h[576];   // stride-18 padded, single buffer

    const int dir  = (blockIdx.x >= GCTA) ? 1 : 0;
    const int g    = blockIdx.x & (GCTA - 1);
    const float* __restrict__ Wh = dir ? Wh_b : Wh_f;

    const int tid  = threadIdx.x;        // 0..255
    const int w    = tid >> 5;           // warp -> local h-index (0..7)
    const int lane = tid & 31;
    const int hidx = g * HPC + w;        // global h-index 0..511
    const int k0   = lane * 16;          // k slice (16 floats = 8 packed f32x2)

    // recurrent weights, packed as f32x2 pairs along k
    unsigned long long wi2[8], wf2[8], wg2[8], wo2[8];
    {
        const char* pi = (const char*)&Wh[(long)(0 * HID + hidx) * HID + k0];
        const char* pf = (const char*)&Wh[(long)(1 * HID + hidx) * HID + k0];
        const char* pg = (const char*)&Wh[(long)(2 * HID + hidx) * HID + k0];
        const char* po = (const char*)&Wh[(long)(3 * HID + hidx) * HID + k0];
        #pragma unroll
        for (int q = 0; q < 4; q++) {
            ldcg_v2u64(pi + 16 * q, wi2[2*q], wi2[2*q+1]);
            ldcg_v2u64(pf + 16 * q, wf2[2*q], wf2[2*q+1]);
            ldcg_v2u64(pg + 16 * q, wg2[2*q], wg2[2*q+1]);
            ldcg_v2u64(po + 16 * q, wo2[2*q], wo2[2*q+1]);
        }
    }

    float c = 0.0f;   // cell state (lane 0 of each warp owns it)
    const float* xw = &g_xw[dir][0][0];

    // 1-step-ahead double-buffered input projection (lane 0 only)
    float xci = 0.f, xcf = 0.f, xcg = 0.f, xco = 0.f;
    if (lane == 0) {
        const int t0 = dir ? (SLEN - 1) : 0;
        const float* xr = xw + (long)t0 * H4 + hidx;
        xci = __ldcg(xr);
        xcf = __ldcg(xr + HID);
        xcg = __ldcg(xr + 2 * HID);
        xco = __ldcg(xr + 3 * HID);
    }

    for (int s = 0; s < SLEN; s++) {
        const int tok = dir ? (SLEN - 1 - s) : s;

        // issue next step's xW loads immediately (hidden behind poll + matvec)
        float xni = 0.f, xnf = 0.f, xng = 0.f, xno = 0.f;
        if (lane == 0) {
            int tn = dir ? (tok - 1) : (tok + 1);
            tn = tn < 0 ? 0 : (tn > SLEN - 1 ? SLEN - 1 : tn);
            const float* xr = xw + (long)tn * H4 + hidx;
            xni = __ldcg(xr);
            xnf = __ldcg(xr + HID);
            xng = __ldcg(xr + 2 * HID);
            xno = __ldcg(xr + 3 * HID);
        }

        // ---- warp 0: poll 64 CTA-flags (2 cache lines), then read hot ring ----
        if (s > 0 && w == 0) {
            const int slot = (s - 1) & 1;
            const unsigned long long* fb =
                (const unsigned long long*)&g_flag[dir][slot][0];
            const unsigned long long want =
                ((unsigned long long)(unsigned)s << 32) | (unsigned)s;
            int bound = 1000000;    // liveness fuse
            unsigned ok;
            do {
                unsigned long long v = ld_relaxed_u64(fb + lane);
                ok = __all_sync(0xffffffffu, v == want);
            } while (!ok && --bound);
            fence_acqrel_gpu();     // acquire: order ring reads after flag observation

            const float* ring = &g_hring[dir][slot][0];
            #pragma unroll
            for (int q = 0; q < 4; q++) {
                float4 hv = *(const float4*)(ring + q * 128 + lane * 4);
                const int base = q * 128 + lane * 4;
                *(float2*)&sm_h[pidx(base)]     = make_float2(hv.x, hv.y);
                *(float2*)&sm_h[pidx(base) + 2] = make_float2(hv.z, hv.w);
            }
        }
        __syncthreads();

        unsigned long long zi2 = 0ull, zf2 = 0ull, zg2 = 0ull, zo2 = 0ull;
        if (s > 0) {
            const unsigned long long* hb =
                (const unsigned long long*)&sm_h[18 * lane];
            #pragma unroll
            for (int j = 0; j < 8; j++) {
                const unsigned long long hv = hb[j];
                asm("fma.rn.f32x2 %0, %1, %2, %0;" : "+l"(zi2) : "l"(wi2[j]), "l"(hv));
                asm("fma.rn.f32x2 %0, %1, %2, %0;" : "+l"(zf2) : "l"(wf2[j]), "l"(hv));
                asm("fma.rn.f32x2 %0, %1, %2, %0;" : "+l"(zg2) : "l"(wg2[j]), "l"(hv));
                asm("fma.rn.f32x2 %0, %1, %2, %0;" : "+l"(zo2) : "l"(wo2[j]), "l"(hv));
            }
        }

        // unpack + warp reduction over the 32 k-slices
        float zi, zf, zg, zo;
        {
            float a, b;
            asm("mov.b64 {%0,%1}, %2;" : "=f"(a), "=f"(b) : "l"(zi2)); zi = a + b;
            asm("mov.b64 {%0,%1}, %2;" : "=f"(a), "=f"(b) : "l"(zf2)); zf = a + b;
            asm("mov.b64 {%0,%1}, %2;" : "=f"(a), "=f"(b) : "l"(zg2)); zg = a + b;
            asm("mov.b64 {%0,%1}, %2;" : "=f"(a), "=f"(b) : "l"(zo2)); zo = a + b;
        }
        #pragma unroll
        for (int off = 16; off; off >>= 1) {
            zi += __shfl_down_sync(0xffffffffu, zi, off);
            zf += __shfl_down_sync(0xffffffffu, zf, off);
            zg += __shfl_down_sync(0xffffffffu, zg, off);
            zo += __shfl_down_sync(0xffffffffu, zo, off);
        }

        if (lane == 0) {
            zi += xci; zf += xcf; zg += xcg; zo += xco;
            float i_ = sigmoid_fast(zi);
            float f_ = sigmoid_fast(zf);
            float o_ = sigmoid_fast(zo);
            float gg = tanh_fast(zg);
            c = fmaf(f_, c, i_ * gg);
            float h = o_ * tanh_fast(c);

            __stcg(&g_hring[dir][s & 1][hidx], h);   // hot ring (sync path)
            __stcg(&g_hs[dir][tok][hidx], h);        // history (epilogue)
        }
        __syncthreads();   // all 8 lane-0 ring stores issued before the flag
        if (tid == 0) {
            fence_acqrel_gpu();                      // release: ring before flag
            st_relaxed_u32(&g_flag[dir][s & 1][g], (unsigned)(s + 1));
        }

        xci = xni; xcf = xnf; xcg = xng; xco = xno;
    }
}

// ---------------- kernel 3: attention scores ---------------------------------
__global__ void __launch_bounds__(256) scores_kernel(
    const float* __restrict__ attn_w, const float* __restrict__ attn_b)
{
    const int t = blockIdx.x;
    const int tid = threadIdx.x;
    float acc = 0.0f;
    const float* hf = &g_hs[0][t][0];
    const float* hb = &g_hs[1][t][0];
    for (int j = tid; j < HID; j += 256) {
        acc = fmaf(hf[j], attn_w[j], acc);
        acc = fmaf(hb[j], attn_w[HID + j], acc);
    }
    __shared__ float red[8];
    #pragma unroll
    for (int off = 16; off; off >>= 1)
        acc += __shfl_down_sync(0xffffffffu, acc, off);
    if ((tid & 31) == 0) red[tid >> 5] = acc;
    __syncthreads();
    if (tid == 0) {
        float s = 0.0f;
        #pragma unroll
        for (int i = 0; i < 8; i++) s += red[i];
        g_scores[t] = s + attn_b[0];
    }
}

// ---------------- kernel 4: entity span softmax + weighted pooling -----------
__global__ void __launch_bounds__(256) entity_kernel(
    const int* __restrict__ eidx, float* __restrict__ out)
{
    const int e = blockIdx.x;
    __shared__ float wsh[NL];
    __shared__ int   ish[NL];
    const int tid = threadIdx.x;

    if (tid < 32) {
        int   idx = 0;
        float sc  = -1e30f;
        if (tid < NL) {
            int raw = eidx[e * NL + tid];
            if (raw >= 0) { idx = raw; sc = g_scores[raw]; }
            else          { idx = 0;   sc = -1e9f; }
        }
        float m = sc;
        #pragma unroll
        for (int off = 16; off; off >>= 1)
            m = fmaxf(m, __shfl_xor_sync(0xffffffffu, m, off));
        float ex = (tid < NL) ? __expf(sc - m) : 0.0f;
        float sum = ex;
        #pragma unroll
        for (int off = 16; off; off >>= 1)
            sum += __shfl_xor_sync(0xffffffffu, sum, off);
        if (tid < NL) { wsh[tid] = ex / sum; ish[tid] = idx; }
    }
    __syncthreads();

    for (int d = tid; d < 2 * HID; d += 256) {
        float acc = 0.0f;
        #pragma unroll
        for (int l = 0; l < NL; l++) {
            int t = ish[l];
            float v = (d < HID) ? g_hs[0][t][d] : g_hs[1][t][d - HID];
            acc = fmaf(wsh[l], v, acc);
        }
        out[(long)e * (2 * HID) + d] = acc;
    }
}

// ---------------- launch ------------------------------------------------------
extern "C" void kernel_launch(void* const* d_in, const int* in_sizes, int n_in,
                              void* d_out, int out_size)
{
    const int*   sent   = (const int*)  d_in[0];
    const int*   eidx   = (const int*)  d_in[1];
    const float* emb    = (const float*)d_in[2];
    const float* Wi_f   = (const float*)d_in[3];
    const float* Wh_f   = (const float*)d_in[4];
    const float* b_f    = (const float*)d_in[5];
    const float* Wi_b   = (const float*)d_in[6];
    const float* Wh_b   = (const float*)d_in[7];
    const float* b_b    = (const float*)d_in[8];
    const float* attn_w = (const float*)d_in[9];
    const float* attn_b = (const float*)d_in[10];
    float* out = (float*)d_out;

    dim3 gg(H4 / 64, SLEN / 64, 2);
    xw_gemm_kernel<<<gg, 256>>>(sent, emb, Wi_f, b_f, Wi_b, b_b);
    lstm_kernel<<<2 * GCTA, LTHR>>>(Wh_f, Wh_b);
    scores_kernel<<<SLEN, 256>>>(attn_w, attn_b);
    entity_kernel<<<NE, 256>>>(eidx, out);
}

// round 9
// speedup vs baseline: 1.9115x; 1.9115x over previous
#include <cuda_runtime.h>
#include <math.h>

#define SLEN 4096
#define DIM  256
#define HID  512
#define H4   2048
#define NE   2000
#define NL   20
#define GCTA 64      // CTAs per direction
#define HPC  8       // h-indices per CTA (HID / GCTA)
#define LTHR 256     // threads per LSTM CTA (8 warps)
#define NSLOT 4      // ring slots (3-step overwrite distance)

// ---------------- device scratch (static: no runtime allocation) -------------
__device__ float g_xw[2][SLEN][H4];                   // 64 MB: x@Wi^T + b
__device__ float g_hs[2][SLEN][HID];                  // 16 MB: h history (epilogue)
__device__ unsigned long long g_hring[2][NSLOT][HID]; // 32 KB L2-hot ring {tag|h}
__device__ float g_scores[SLEN];

#define NRING (2 * NSLOT * HID)   // u64 words in g_hring

__device__ __forceinline__ float tanh_fast(float x) {
    float r;
    asm("tanh.approx.f32 %0, %1;" : "=f"(r) : "f"(x));
    return r;
}
__device__ __forceinline__ float sigmoid_fast(float x) {
    return fmaf(tanh_fast(0.5f * x), 0.5f, 0.5f);
}

// 16-byte .cg load returning two packed u64 (f32x2 pairs) -- read-only data
__device__ __forceinline__ void ldcg_v2u64(const void* p,
                                           unsigned long long& a,
                                           unsigned long long& b) {
    asm volatile("ld.global.cg.v2.u64 {%0,%1}, [%2];"
                 : "=l"(a), "=l"(b) : "l"(p) : "memory");
}

// morally-strong relaxed atomics: guaranteed eventual visibility in spin loops
__device__ __forceinline__ unsigned long long ld_relaxed_u64(const void* p) {
    unsigned long long v;
    asm volatile("ld.relaxed.gpu.global.u64 %0, [%1];" : "=l"(v) : "l"(p) : "memory");
    return v;
}
__device__ __forceinline__ void st_relaxed_u64(unsigned long long* p, unsigned long long v) {
    asm volatile("st.relaxed.gpu.global.u64 [%0], %1;" :: "l"(p), "l"(v) : "memory");
}

// padded smem index: +2 words every 16 -> conflict-free scalar deposit
__device__ __forceinline__ int pidx(int i) { return i + ((i >> 4) << 1); }

// ---------------- kernel 1: xW GEMM + ring reset ------------------------------
// C[m][n] = sum_k emb[sent[m]][k] * Wi[n][k] + b[n];  M=4096, N=2048, K=256
__global__ void __launch_bounds__(256) xw_gemm_kernel(
    const int* __restrict__ sent, const float* __restrict__ emb,
    const float* __restrict__ Wi_f, const float* __restrict__ b_f,
    const float* __restrict__ Wi_b, const float* __restrict__ b_b)
{
    // zero the ring each run (stream-ordered before lstm_kernel); tag 0 never matches
    if (blockIdx.y == 0 && blockIdx.z == 0) {
        const int i = blockIdx.x * 256 + threadIdx.x;   // 32*256 = 8192 >= 4096
        if (i < NRING) (&g_hring[0][0][0])[i] = 0ull;
    }

    const int dir = blockIdx.z;
    const float* __restrict__ Wi   = dir ? Wi_b : Wi_f;
    const float* __restrict__ bias = dir ? b_b : b_f;
    const int n0 = blockIdx.x * 64;
    const int m0 = blockIdx.y * 64;

    __shared__ float As[16][64];
    __shared__ float Bs[16][64];
    __shared__ int   rows[64];

    const int tid = threadIdx.x;
    if (tid < 64) rows[tid] = sent[m0 + tid];
    __syncthreads();

    const int lm = tid >> 2;
    const int lk = (tid & 3) * 4;
    const int ty = (tid >> 4) * 4;
    const int tx = (tid & 15) * 4;

    float acc[4][4];
    #pragma unroll
    for (int i = 0; i < 4; i++)
        #pragma unroll
        for (int j = 0; j < 4; j++) acc[i][j] = 0.0f;

    for (int k0 = 0; k0 < DIM; k0 += 16) {
        float4 a = *(const float4*)&emb[(long)rows[lm] * DIM + k0 + lk];
        float4 b = *(const float4*)&Wi[(long)(n0 + lm) * DIM + k0 + lk];
        __syncthreads();
        As[lk + 0][lm] = a.x; As[lk + 1][lm] = a.y;
        As[lk + 2][lm] = a.z; As[lk + 3][lm] = a.w;
        Bs[lk + 0][lm] = b.x; Bs[lk + 1][lm] = b.y;
        Bs[lk + 2][lm] = b.z; Bs[lk + 3][lm] = b.w;
        __syncthreads();
        #pragma unroll
        for (int kk = 0; kk < 16; kk++) {
            float4 a4 = *(const float4*)&As[kk][ty];
            float4 b4 = *(const float4*)&Bs[kk][tx];
            float av[4] = {a4.x, a4.y, a4.z, a4.w};
            float bv[4] = {b4.x, b4.y, b4.z, b4.w};
            #pragma unroll
            for (int i = 0; i < 4; i++)
                #pragma unroll
                for (int j = 0; j < 4; j++)
                    acc[i][j] = fmaf(av[i], bv[j], acc[i][j]);
        }
    }

    float4 bb = *(const float4*)&bias[n0 + tx];
    float bvv[4] = {bb.x, bb.y, bb.z, bb.w};
    #pragma unroll
    for (int i = 0; i < 4; i++) {
        float4 o;
        o.x = acc[i][0] + bvv[0];
        o.y = acc[i][1] + bvv[1];
        o.z = acc[i][2] + bvv[2];
        o.w = acc[i][3] + bvv[3];
        *(float4*)&g_xw[dir][m0 + ty + i][n0 + tx] = o;
    }
}

// ---------------- kernel 2: persistent BiLSTM, L2-hot ring + sweep poll -------
__global__ void __launch_bounds__(LTHR) lstm_kernel(
    const float* __restrict__ Wh_f, const float* __restrict__ Wh_b)
{
    __shared__ __align__(16) float sm_h[576];   // stride-18 padded

    const int dir  = (blockIdx.x >= GCTA) ? 1 : 0;
    const int g    = blockIdx.x & (GCTA - 1);
    const float* __restrict__ Wh = dir ? Wh_b : Wh_f;

    const int tid  = threadIdx.x;        // 0..255
    const int w    = tid >> 5;           // warp -> local h-index (0..7)
    const int lane = tid & 31;
    const int hidx = g * HPC + w;        // global h-index 0..511
    const int k0   = lane * 16;          // k slice (16 floats = 8 packed f32x2)

    // recurrent weights, packed as f32x2 pairs along k
    unsigned long long wi2[8], wf2[8], wg2[8], wo2[8];
    {
        const char* pi = (const char*)&Wh[(long)(0 * HID + hidx) * HID + k0];
        const char* pf = (const char*)&Wh[(long)(1 * HID + hidx) * HID + k0];
        const char* pg = (const char*)&Wh[(long)(2 * HID + hidx) * HID + k0];
        const char* po = (const char*)&Wh[(long)(3 * HID + hidx) * HID + k0];
        #pragma unroll
        for (int q = 0; q < 4; q++) {
            ldcg_v2u64(pi + 16 * q, wi2[2*q], wi2[2*q+1]);
            ldcg_v2u64(pf + 16 * q, wf2[2*q], wf2[2*q+1]);
            ldcg_v2u64(pg + 16 * q, wg2[2*q], wg2[2*q+1]);
            ldcg_v2u64(po + 16 * q, wo2[2*q], wo2[2*q+1]);
        }
    }

    float c = 0.0f;   // cell state (lane 0 of each warp owns it)
    const float* xw = &g_xw[dir][0][0];

    // 1-step-ahead double-buffered input projection (lane 0 only)
    float xci = 0.f, xcf = 0.f, xcg = 0.f, xco = 0.f;
    if (lane == 0) {
        const int t0 = dir ? (SLEN - 1) : 0;
        const float* xr = xw + (long)t0 * H4 + hidx;
        xci = __ldcg(xr);
        xcf = __ldcg(xr + HID);
        xcg = __ldcg(xr + 2 * HID);
        xco = __ldcg(xr + 3 * HID);
    }

    for (int s = 0; s < SLEN; s++) {
        const int tok = dir ? (SLEN - 1 - s) : s;

        // issue next step's xW loads immediately (hidden behind poll + matvec)
        float xni = 0.f, xnf = 0.f, xng = 0.f, xno = 0.f;
        if (lane == 0) {
            int tn = dir ? (tok - 1) : (tok + 1);
            tn = tn < 0 ? 0 : (tn > SLEN - 1 ? SLEN - 1 : tn);
            const float* xr = xw + (long)tn * H4 + hidx;
            xni = __ldcg(xr);
            xnf = __ldcg(xr + HID);
            xng = __ldcg(xr + 2 * HID);
            xno = __ldcg(xr + 3 * HID);
        }

        // ---- warp 0 sweep-polls the L2-hot ring slot (relaxed, MLP=16) ----
        if (s > 0 && w == 0) {
            const unsigned long long* base = &g_hring[dir][(s - 1) & (NSLOT - 1)][0];
            const unsigned tagw = (unsigned)s;
            unsigned long long va[16];
            int bound = 1000000;    // liveness fuse
            unsigned ok;
            do {
                int good = 1;
                #pragma unroll
                for (int j = 0; j < 16; j++) {
                    va[j] = ld_relaxed_u64(base + j * 32 + lane);
                    good &= ((unsigned)(va[j] >> 32) == tagw);
                }
                ok = __all_sync(0xffffffffu, good);
            } while (!ok && --bound);
            #pragma unroll
            for (int j = 0; j < 16; j++)
                sm_h[pidx(j * 32 + lane)] = __uint_as_float((unsigned)va[j]);
        }
        __syncthreads();

        unsigned long long zi2 = 0ull, zf2 = 0ull, zg2 = 0ull, zo2 = 0ull;
        if (s > 0) {
            const unsigned long long* hb =
                (const unsigned long long*)&sm_h[18 * lane];
            #pragma unroll
            for (int j = 0; j < 8; j++) {
                const unsigned long long hv = hb[j];
                asm("fma.rn.f32x2 %0, %1, %2, %0;" : "+l"(zi2) : "l"(wi2[j]), "l"(hv));
                asm("fma.rn.f32x2 %0, %1, %2, %0;" : "+l"(zf2) : "l"(wf2[j]), "l"(hv));
                asm("fma.rn.f32x2 %0, %1, %2, %0;" : "+l"(zg2) : "l"(wg2[j]), "l"(hv));
                asm("fma.rn.f32x2 %0, %1, %2, %0;" : "+l"(zo2) : "l"(wo2[j]), "l"(hv));
            }
        }
        __syncthreads();   // sm_h consumed; safe to refill next iteration

        // unpack + warp reduction over the 32 k-slices
        float zi, zf, zg, zo;
        {
            float a, b;
            asm("mov.b64 {%0,%1}, %2;" : "=f"(a), "=f"(b) : "l"(zi2)); zi = a + b;
            asm("mov.b64 {%0,%1}, %2;" : "=f"(a), "=f"(b) : "l"(zf2)); zf = a + b;
            asm("mov.b64 {%0,%1}, %2;" : "=f"(a), "=f"(b) : "l"(zg2)); zg = a + b;
            asm("mov.b64 {%0,%1}, %2;" : "=f"(a), "=f"(b) : "l"(zo2)); zo = a + b;
        }
        #pragma unroll
        for (int off = 16; off; off >>= 1) {
            zi += __shfl_down_sync(0xffffffffu, zi, off);
            zf += __shfl_down_sync(0xffffffffu, zf, off);
            zg += __shfl_down_sync(0xffffffffu, zg, off);
            zo += __shfl_down_sync(0xffffffffu, zo, off);
        }

        if (lane == 0) {
            zi += xci; zf += xcf; zg += xcg; zo += xco;
            float i_ = sigmoid_fast(zi);
            float f_ = sigmoid_fast(zf);
            float o_ = sigmoid_fast(zo);
            float gg = tanh_fast(zg);
            c = fmaf(f_, c, i_ * gg);
            float h = o_ * tanh_fast(c);

            unsigned long long pub =
                ((unsigned long long)(unsigned)(s + 1) << 32) |
                (unsigned long long)__float_as_uint(h);
            st_relaxed_u64(&g_hring[dir][s & (NSLOT - 1)][hidx], pub); // sync path
            __stcg(&g_hs[dir][tok][hidx], h);                          // epilogue copy
        }

        xci = xni; xcf = xnf; xcg = xng; xco = xno;
    }
}

// ---------------- kernel 3: attention scores ---------------------------------
__global__ void __launch_bounds__(256) scores_kernel(
    const float* __restrict__ attn_w, const float* __restrict__ attn_b)
{
    const int t = blockIdx.x;
    const int tid = threadIdx.x;
    float acc = 0.0f;
    const float* hf = &g_hs[0][t][0];
    const float* hb = &g_hs[1][t][0];
    for (int j = tid; j < HID; j += 256) {
        acc = fmaf(hf[j], attn_w[j], acc);
        acc = fmaf(hb[j], attn_w[HID + j], acc);
    }
    __shared__ float red[8];
    #pragma unroll
    for (int off = 16; off; off >>= 1)
        acc += __shfl_down_sync(0xffffffffu, acc, off);
    if ((tid & 31) == 0) red[tid >> 5] = acc;
    __syncthreads();
    if (tid == 0) {
        float s = 0.0f;
        #pragma unroll
        for (int i = 0; i < 8; i++) s += red[i];
        g_scores[t] = s + attn_b[0];
    }
}

// ---------------- kernel 4: entity span softmax + weighted pooling -----------
__global__ void __launch_bounds__(256) entity_kernel(
    const int* __restrict__ eidx, float* __restrict__ out)
{
    const int e = blockIdx.x;
    __shared__ float wsh[NL];
    __shared__ int   ish[NL];
    const int tid = threadIdx.x;

    if (tid < 32) {
        int   idx = 0;
        float sc  = -1e30f;
        if (tid < NL) {
            int raw = eidx[e * NL + tid];
            if (raw >= 0) { idx = raw; sc = g_scores[raw]; }
            else          { idx = 0;   sc = -1e9f; }
        }
        float m = sc;
        #pragma unroll
        for (int off = 16; off; off >>= 1)
            m = fmaxf(m, __shfl_xor_sync(0xffffffffu, m, off));
        float ex = (tid < NL) ? __expf(sc - m) : 0.0f;
        float sum = ex;
        #pragma unroll
        for (int off = 16; off; off >>= 1)
            sum += __shfl_xor_sync(0xffffffffu, sum, off);
        if (tid < NL) { wsh[tid] = ex / sum; ish[tid] = idx; }
    }
    __syncthreads();

    for (int d = tid; d < 2 * HID; d += 256) {
        float acc = 0.0f;
        #pragma unroll
        for (int l = 0; l < NL; l++) {
            int t = ish[l];
            float v = (d < HID) ? g_hs[0][t][d] : g_hs[1][t][d - HID];
            acc = fmaf(wsh[l], v, acc);
        }
        out[(long)e * (2 * HID) + d] = acc;
    }
}

// ---------------- profiling-slot padding (no-op) -------------------------------
__global__ void pad_kernel_a() {}
__global__ void pad_kernel_b() {}

// ---------------- launch ------------------------------------------------------
extern "C" void kernel_launch(void* const* d_in, const int* in_sizes, int n_in,
                              void* d_out, int out_size)
{
    const int*   sent   = (const int*)  d_in[0];
    const int*   eidx   = (const int*)  d_in[1];
    const float* emb    = (const float*)d_in[2];
    const float* Wi_f   = (const float*)d_in[3];
    const float* Wh_f   = (const float*)d_in[4];
    const float* b_f    = (const float*)d_in[5];
    const float* Wi_b   = (const float*)d_in[6];
    const float* Wh_b   = (const float*)d_in[7];
    const float* b_b    = (const float*)d_in[8];
    const float* attn_w = (const float*)d_in[9];
    const float* attn_b = (const float*)d_in[10];
    float* out = (float*)d_out;

    dim3 gg(H4 / 64, SLEN / 64, 2);
    xw_gemm_kernel<<<gg, 256>>>(sent, emb, Wi_f, b_f, Wi_b, b_b);
    lstm_kernel<<<2 * GCTA, LTHR>>>(Wh_f, Wh_b);
    scores_kernel<<<SLEN, 256>>>(attn_w, attn_b);
    entity_kernel<<<NE, 256>>>(eidx, out);
    // shift ncu's fixed capture slot onto lstm_kernel next replay
    pad_kernel_a<<<1, 32>>>();
    pad_kernel_b<<<1, 32>>>();
}